// round 16
// baseline (speedup 1.0000x reference)
#include <cuda_runtime.h>
#include <cuda_fp16.h>
#include <math.h>
#include <stdint.h>

#define EE 4
#define NTOK 2048
#define DD 512
#define HH 8
#define DHH 64
#define FFD 2048
#define LL 4
#define MMEM 4096

typedef __half f16;

// ---------------- static scratch ----------------
__device__ float g_xln[EE * NTOK * DD];
__device__ float g_x[EE * NTOK * DD];
__device__ float g_y[EE * NTOK * DD];
__device__ float g_upd4[(size_t)EE * LL * MMEM * DD];
__device__ float g_pooled[EE * DD];
__device__ float g_gatew[EE];
__device__ float2 g_part[4194304];     // per-(row, slot) softmax partials
__device__ float2 g_stat[EE * HH * NTOK]; // per-row (max, 1/sum)

__device__ f16 g_xlnh[EE * NTOK * DD];
__device__ f16 g_xh[EE * NTOK * DD];
__device__ f16 g_qkvh[EE * NTOK * 3 * DD];
__device__ f16 g_sah[EE * NTOK * DD];
__device__ f16 g_ff1h[EE * NTOK * FFD];
__device__ f16 g_sch[(size_t)EE * HH * NTOK * NTOK];   // raw clipped scores
__device__ f16 g_retrph[EE * NTOK * LL * DD];
__device__ f16 g_memh[LL * MMEM * DD];
__device__ f16 g_ipwh[EE * 3 * DD * DD];
__device__ f16 g_opwh[EE * DD * DD];
__device__ f16 g_w1h[EE * FFD * DD];
__device__ f16 g_w2h[EE * DD * FFD];
__device__ f16 g_aggwh[DD * LL * DD];

__device__ __forceinline__ uint32_t smem_u32(const void* p) {
    uint32_t a;
    asm("{ .reg .u64 t; cvta.to.shared.u64 t, %1; cvt.u32.u64 %0, t; }" : "=r"(a) : "l"(p));
    return a;
}

#define MMA16816(d, a0, a1, a2, a3, b0, b1) \
    asm volatile("mma.sync.aligned.m16n8k16.row.col.f32.f16.f16.f32 " \
                 "{%0,%1,%2,%3}, {%4,%5,%6,%7}, {%8,%9}, {%0,%1,%2,%3};" \
                 : "+f"((d)[0]), "+f"((d)[1]), "+f"((d)[2]), "+f"((d)[3]) \
                 : "r"(a0), "r"(a1), "r"(a2), "r"(a3), "r"(b0), "r"(b1))

#define LDSM4(r0, r1, r2, r3, addr) \
    asm volatile("ldmatrix.sync.aligned.m8n8.x4.shared.b16 {%0,%1,%2,%3}, [%4];" \
                 : "=r"(r0), "=r"(r1), "=r"(r2), "=r"(r3) : "r"(addr))

#define LDSM4T(r0, r1, r2, r3, addr) \
    asm volatile("ldmatrix.sync.aligned.m8n8.x4.trans.shared.b16 {%0,%1,%2,%3}, [%4];" \
                 : "=r"(r0), "=r"(r1), "=r"(r2), "=r"(r3) : "r"(addr))

#define CP16(dst, src) \
    asm volatile("cp.async.cg.shared.global [%0], [%1], 16;" :: "r"(dst), "l"(src))
#define CPCOMMIT() asm volatile("cp.async.commit_group;")
#define CPWAIT(n)  asm volatile("cp.async.wait_group %0;" :: "n"(n))

// ---------------- HMMA fp16 GEMM with fused-softmax hooks ----------------
// SOFT: epilogue also emits per-(row, warp-slice) (max, sumexp) partials.
// EXA : A operand is raw scores; fill transforms a -> __expf(a - M) * inv using
//       per-row stats (register-prefetched LDG one k-tile ahead; B stays cp.async).
template<int BN, int STAGES, int TA, int TB, int SOFT, int EXA>
__global__ void __launch_bounds__(256, 2) hgemm(
    const f16* __restrict__ Ahg, const f16* __restrict__ Bhg,
    float* __restrict__ C, f16* __restrict__ Ch,
    int Kdim, int Arow, int Brow, int ldc,
    float alpha, int ep,
    const float* __restrict__ bias, long biasZ, const float* __restrict__ Rres,
    int nRemap, int kRemap, int thresh, int inner,
    long Ai, long Ao, long Bi, long Bo, long Ci, long Co,
    const float2* __restrict__ stat, float2* __restrict__ part, int slotTot)
{
    constexpr int AST = 128 * 80;
    constexpr int BST = BN * 80;
    constexpr int NT = BN / 32;
    constexpr int BIT = BN / 64;
    constexpr int ASTR = 272;
    constexpr int BSTR = BN * 2 + 16;
    constexpr int BCH = BN / 8;

    const int z1 = blockIdx.z % inner;
    const int z2 = blockIdx.z / inner;
    Ahg += (long)z1 * Ai + (long)z2 * Ao;
    Bhg += (long)z1 * Bi + (long)z2 * Bo;
    const long coff = (long)z1 * Ci + (long)z2 * Co;
    if (C)  C  += coff;
    if (Ch) Ch += coff;
    if (Rres) Rres += coff;
    if (bias) bias += (long)z2 * biasZ;
    const int th = (thresh < 0) ? z2 * NTOK : thresh;
    const long statB = (long)blockIdx.z * NTOK;

    extern __shared__ char sm[];
    const uint32_t smBase = smem_u32(sm);
    const uint32_t offAh = 0;
    const uint32_t offBh = STAGES * AST;

    const int tid = threadIdx.x;
    const int lane = tid & 31;
    const int wid = tid >> 5;
    const int wm = (wid >> 2) * 64;
    const int wn = (wid & 3) * (BN / 4);
    const int row0 = blockIdx.y * 128;
    const int col0 = blockIdx.x * BN;

    const int g = lane >> 3;
    const uint32_t laneOffA = TA
        ? ((lane & 7) + (g >> 1) * 8) * ASTR + (g & 1) * 16
        : ((g & 1) * 8 + (lane & 7)) * 80 + (g >> 1) * 16;
    const uint32_t laneOffB = TB
        ? ((lane & 7) + (g >> 1) * 8) * BSTR + (g & 1) * 16
        : ((g & 1) * 8 + (lane & 7)) * 80 + (g >> 1) * 16;

    float acc[4][NT][4];
    #pragma unroll
    for (int i = 0; i < 4; i++)
        #pragma unroll
        for (int j = 0; j < NT; j++)
            #pragma unroll
            for (int r = 0; r < 4; r++) acc[i][j][r] = 0.f;

    uint4 areg[2];
    float2 streg[2];

    auto fillA_cp = [&](int s, int t) {
        int k0 = t * 32;
        if (!TA) {
            #pragma unroll
            for (int r = 0; r < 2; r++) {
                int idx = tid + r * 256;
                int row = idx >> 2, c = idx & 3;
                long go = (long)(row0 + row) * Arow + k0 + c * 8;
                CP16(smBase + offAh + s * AST + row * 80 + c * 16, Ahg + go);
            }
        } else {
            #pragma unroll
            for (int r = 0; r < 2; r++) {
                int idx = tid + r * 256;
                int row = idx >> 4, c = idx & 15;
                long go = (long)(k0 + row) * Arow + row0 + c * 8;
                CP16(smBase + offAh + s * AST + row * ASTR + c * 16, Ahg + go);
            }
        }
    };
    auto fillA_regs = [&](int t) {
        int k0 = t * 32;
        #pragma unroll
        for (int r = 0; r < 2; r++) {
            int idx = tid + r * 256;
            if (!TA) {
                int row = idx >> 2, c = idx & 3;
                long grow = row0 + row;
                areg[r] = *(const uint4*)(Ahg + grow * Arow + k0 + c * 8);
                streg[r] = stat[statB + grow];
            } else {
                int row = idx >> 4, c = idx & 15;
                long gk = k0 + row;
                areg[r] = *(const uint4*)(Ahg + gk * Arow + row0 + c * 8);
                streg[r] = stat[statB + gk];
            }
        }
    };
    auto fillA_sts = [&](int s) {
        #pragma unroll
        for (int r = 0; r < 2; r++) {
            int idx = tid + r * 256;
            uint32_t off;
            if (!TA) { int row = idx >> 2, c = idx & 3;  off = offAh + s * AST + row * 80 + c * 16; }
            else     { int row = idx >> 4, c = idx & 15; off = offAh + s * AST + row * ASTR + c * 16; }
            const __half2* hp = (const __half2*)&areg[r];
            const float M = streg[r].x, inv = streg[r].y;
            __half2 o[4];
            #pragma unroll
            for (int q = 0; q < 4; q++) {
                float2 f2 = __half22float2(hp[q]);
                o[q] = __halves2half2(__float2half_rn(__expf(f2.x - M) * inv),
                                      __float2half_rn(__expf(f2.y - M) * inv));
            }
            *(uint4*)(sm + off) = *(const uint4*)o;
        }
    };
    auto fillB = [&](int s, int t) {
        int k0 = t * 32;
        if (!TB) {
            long kb = k0 + ((kRemap && k0 >= th) ? NTOK : 0);
            #pragma unroll
            for (int r = 0; r < BIT; r++) {
                int idx = tid + r * 256;
                int row = idx >> 2, c = idx & 3;
                int ng = col0 + row;
                if (nRemap && ng >= th) ng += NTOK;
                long go = (long)ng * Brow + kb + c * 8;
                CP16(smBase + offBh + s * BST + row * 80 + c * 16, Bhg + go);
            }
        } else {
            #pragma unroll
            for (int r = 0; r < BIT; r++) {
                int idx = tid + r * 256;
                int row = idx / BCH, c = idx % BCH;
                int kg = k0 + row;
                if (kRemap && kg >= th) kg += NTOK;
                long go = (long)kg * Brow + col0 + c * 8;
                CP16(smBase + offBh + s * BST + row * BSTR + c * 16, Bhg + go);
            }
        }
    };

    auto compute = [&](int buf) {
        const uint32_t aH = smBase + offAh + buf * AST + laneOffA;
        const uint32_t bH = smBase + offBh + buf * BST + laneOffB;
        #pragma unroll
        for (int s = 0; s < 2; s++) {
            uint32_t bh[NT][2];
            #pragma unroll
            for (int p = 0; p < NT / 2; p++) {
                uint32_t addr = TB ? bH + s * (16 * BSTR) + (wn + p * 16) * 2
                                   : bH + (wn + p * 16) * 80 + s * 32;
                if (TB) { LDSM4T(bh[2*p][0], bh[2*p+1][0], bh[2*p][1], bh[2*p+1][1], addr); }
                else    { LDSM4 (bh[2*p][0], bh[2*p+1][0], bh[2*p][1], bh[2*p+1][1], addr); }
            }
            #pragma unroll
            for (int mt = 0; mt < 4; mt++) {
                uint32_t a0, a1, a2, a3;
                uint32_t addr = TA ? aH + s * (16 * ASTR) + (wm + mt * 16) * 2
                                   : aH + (wm + mt * 16) * 80 + s * 32;
                if (TA) { LDSM4T(a0, a1, a2, a3, addr); }
                else    { LDSM4 (a0, a1, a2, a3, addr); }
                #pragma unroll
                for (int nt = 0; nt < NT; nt++)
                    MMA16816(acc[mt][nt], a0, a1, a2, a3, bh[nt][0], bh[nt][1]);
            }
        }
    };

    const int nk = Kdim / 32;
    #pragma unroll
    for (int s = 0; s < STAGES - 1; s++) {
        if (s < nk) {
            if (EXA) { fillA_regs(s); fillA_sts(s); }
            else     fillA_cp(s, s);
            fillB(s, s);
        }
        CPCOMMIT();
    }
    for (int t = 0; t < nk; t++) {
        CPWAIT(STAGES - 2);
        __syncthreads();
        int tn = t + STAGES - 1;
        if (tn < nk) {
            if (EXA) fillA_regs(tn);
            else     fillA_cp(tn % STAGES, tn);
            fillB(tn % STAGES, tn);
        }
        CPCOMMIT();
        compute(t % STAGES);
        if (EXA && tn < nk) fillA_sts(tn % STAGES);
    }

    if (SOFT) {
        // scores: store clipped f16 + per-row (max, sumexp) partials
        const long zM = (long)blockIdx.z * ((long)gridDim.y * 128);
        #pragma unroll
        for (int mt = 0; mt < 4; mt++) {
            #pragma unroll
            for (int hf = 0; hf < 2; hf++) {
                int mg = row0 + wm + mt * 16 + (lane >> 2) + hf * 8;
                float vv[2 * NT];
                float mx = -1e30f;
                #pragma unroll
                for (int nt = 0; nt < NT; nt++) {
                    int ng = col0 + wn + nt * 8 + (lane & 3) * 2;
                    float v0 = acc[mt][nt][hf * 2 + 0] * alpha;
                    float v1 = acc[mt][nt][hf * 2 + 1] * alpha;
                    if (ep == 1) {
                        v0 = fminf(fmaxf(v0, -10.f), 10.f);
                        v1 = fminf(fmaxf(v1, -10.f), 10.f);
                    }
                    *(__half2*)(Ch + (long)mg * ldc + ng) =
                        __halves2half2(__float2half_rn(v0), __float2half_rn(v1));
                    vv[nt * 2] = v0; vv[nt * 2 + 1] = v1;
                    mx = fmaxf(mx, fmaxf(v0, v1));
                }
                mx = fmaxf(mx, __shfl_xor_sync(0xffffffffu, mx, 1));
                mx = fmaxf(mx, __shfl_xor_sync(0xffffffffu, mx, 2));
                float s = 0.f;
                #pragma unroll
                for (int i = 0; i < 2 * NT; i++) s += __expf(vv[i] - mx);
                s += __shfl_xor_sync(0xffffffffu, s, 1);
                s += __shfl_xor_sync(0xffffffffu, s, 2);
                if ((lane & 3) == 0)
                    part[(zM + mg) * slotTot + blockIdx.x * 4 + (wid & 3)] =
                        make_float2(mx, s);
            }
        }
        return;
    }

    // normal epilogue (vectorized: column pairs)
    #pragma unroll
    for (int mt = 0; mt < 4; mt++) {
        #pragma unroll
        for (int nt = 0; nt < NT; nt++) {
            int ng = col0 + wn + nt * 8 + (lane & 3) * 2;
            float2 b2 = make_float2(0.f, 0.f);
            if (ep >= 2 && ep <= 4) b2 = *(const float2*)(bias + ng);
            #pragma unroll
            for (int hf = 0; hf < 2; hf++) {
                int mg = row0 + wm + mt * 16 + (lane >> 2) + hf * 8;
                long ci = (long)mg * ldc + ng;
                float v0 = acc[mt][nt][hf * 2 + 0] * alpha;
                float v1 = acc[mt][nt][hf * 2 + 1] * alpha;
                switch (ep) {
                case 1:
                    v0 = fminf(fmaxf(v0, -10.f), 10.f);
                    v1 = fminf(fmaxf(v1, -10.f), 10.f); break;
                case 2: v0 += b2.x; v1 += b2.y; break;
                case 3:
                    v0 = fmaxf(v0 + b2.x, 0.f);
                    v1 = fmaxf(v1 + b2.y, 0.f); break;
                case 4: {
                    float2 r2 = *(const float2*)(Rres + ci);
                    v0 += b2.x + r2.x; v1 += b2.y + r2.y; } break;
                case 6: {
                    float2 r2 = *(const float2*)(Rres + ci);
                    v0 += r2.x; v1 += r2.y; } break;
                case 7:
                    v0 = fminf(fmaxf(v0, -1.f), 1.f);
                    v1 = fminf(fmaxf(v1, -1.f), 1.f); break;
                }
                if (C) *(float2*)(C + ci) = make_float2(v0, v1);
                if (Ch) *(__half2*)(Ch + ci) =
                    __halves2half2(__float2half_rn(v0), __float2half_rn(v1));
            }
        }
    }
}

// ---------------- softmax partial reduce: per row -> (max, 1/sum) ----------------
__global__ void reduce_stats(const float2* __restrict__ part, float2* __restrict__ stat,
                             int slots, int rows)
{
    int row = blockIdx.x * 8 + (threadIdx.x >> 5);
    if (row >= rows) return;
    int lane = threadIdx.x & 31;
    const float2* p = part + (long)row * slots;
    float M = -1e30f, S = 0.f;
    for (int i = lane; i < slots; i += 32) {
        float2 v = p[i];
        float mn = fmaxf(M, v.x);
        S = S * __expf(M - mn) + v.y * __expf(v.x - mn);
        M = mn;
    }
    #pragma unroll
    for (int o = 16; o; o >>= 1) {
        float Mo = __shfl_xor_sync(0xffffffffu, M, o);
        float So = __shfl_xor_sync(0xffffffffu, S, o);
        float mn = fmaxf(M, Mo);
        S = S * __expf(M - mn) + So * __expf(Mo - mn);
        M = mn;
    }
    if (lane == 0) stat[row] = make_float2(M, 1.f / S);
}

// ---------------- elementwise kernels ----------------
__global__ void convert_kernel(const float* __restrict__ src, f16* __restrict__ h,
                               long n4h)
{
    long i = (long)blockIdx.x * blockDim.x + threadIdx.x;
    if (i >= n4h) return;
    #pragma unroll
    for (int r = 0; r < 2; r++) {
        long j = i + r * n4h;
        float4 v = ((const float4*)src)[j];
        __half2* h2 = (__half2*)h;
        h2[j * 2]     = __halves2half2(__float2half_rn(v.x), __float2half_rn(v.y));
        h2[j * 2 + 1] = __halves2half2(__float2half_rn(v.z), __float2half_rn(v.w));
    }
}

__global__ void ln_kernel(const float* __restrict__ in, float* __restrict__ out,
                          const float* __restrict__ w, const float* __restrict__ b,
                          f16* __restrict__ oh, int wsel)
{
    const long row = blockIdx.x;
    const float* p = in + row * DD;
    const int t = threadIdx.x; // 128
    __shared__ float sh[4];
    const long wo = wsel ? (row / NTOK) * DD : 0;

    float v[4];
    float s = 0.f;
    #pragma unroll
    for (int i = 0; i < 4; i++) { v[i] = p[t + i * 128]; s += v[i]; }
    #pragma unroll
    for (int o = 16; o; o >>= 1) s += __shfl_down_sync(0xffffffffu, s, o);
    if ((t & 31) == 0) sh[t >> 5] = s;
    __syncthreads();
    float mu = (sh[0] + sh[1] + sh[2] + sh[3]) * (1.f / DD);
    __syncthreads();
    float sq = 0.f;
    #pragma unroll
    for (int i = 0; i < 4; i++) { float d = v[i] - mu; sq += d * d; }
    #pragma unroll
    for (int o = 16; o; o >>= 1) sq += __shfl_down_sync(0xffffffffu, sq, o);
    if ((t & 31) == 0) sh[t >> 5] = sq;
    __syncthreads();
    float rstd = rsqrtf((sh[0] + sh[1] + sh[2] + sh[3]) * (1.f / DD) + 1e-5f);

    #pragma unroll
    for (int i = 0; i < 4; i++) {
        int d = t + i * 128;
        float o = (v[i] - mu) * rstd;
        if (w) o = o * w[wo + d] + b[wo + d];
        long gi = row * DD + d;
        if (out) out[gi] = o;
        oh[gi] = __float2half_rn(o);
    }
}

__global__ void pool_kernel(const float* __restrict__ x, float* __restrict__ pooled)
{
    int idx = blockIdx.x * blockDim.x + threadIdx.x;
    if (idx >= EE * DD) return;
    int e = idx / DD, d = idx % DD;
    const float* p = x + (long)e * NTOK * DD + d;
    float s = 0.f;
    #pragma unroll 16
    for (int n = 0; n < NTOK; n++) s += p[(long)n * DD];
    pooled[idx] = s * (1.f / NTOK);
}

__global__ void gate_kernel(const float* __restrict__ pooled, const float* __restrict__ gate,
                            float* __restrict__ out_gw, float* __restrict__ gdev)
{
    const int t = threadIdx.x;
    const int wid = t >> 5, lane = t & 31;
    __shared__ float logits[4];
    float s = 0.f;
    for (int d = lane; d < DD; d += 32) s += pooled[wid * DD + d] * gate[d];
    #pragma unroll
    for (int o = 16; o; o >>= 1) s += __shfl_down_sync(0xffffffffu, s, o);
    if (lane == 0) logits[wid] = fminf(fmaxf(s, -10.f), 10.f);
    __syncthreads();
    if (t == 0) {
        float mx = fmaxf(fmaxf(logits[0], logits[1]), fmaxf(logits[2], logits[3]));
        float e0 = expf(logits[0] - mx), e1 = expf(logits[1] - mx);
        float e2 = expf(logits[2] - mx), e3 = expf(logits[3] - mx);
        float inv = 1.f / (e0 + e1 + e2 + e3);
        out_gw[0] = gdev[0] = e0 * inv;
        out_gw[1] = gdev[1] = e1 * inv;
        out_gw[2] = gdev[2] = e2 * inv;
        out_gw[3] = gdev[3] = e3 * inv;
    }
}

__global__ void fused_kernel(const float* __restrict__ x, const float* __restrict__ gw,
                             float* __restrict__ out)
{
    long i = (long)blockIdx.x * blockDim.x + threadIdx.x;
    if (i >= (long)NTOK * DD) return;
    float s = 0.f;
    #pragma unroll
    for (int e = 0; e < EE; e++) s += gw[e] * x[(long)e * NTOK * DD + i];
    out[i] = s;
}

__global__ void newmem_kernel(const float* __restrict__ mem, const float* __restrict__ upd4,
                              float* __restrict__ out)
{
    long i = (long)blockIdx.x * blockDim.x + threadIdx.x;
    const long S = (long)LL * MMEM * DD;
    if (i >= S) return;
    float u = ((upd4[i] + upd4[i + S]) + upd4[i + 2 * S]) + upd4[i + 3 * S];
    u *= 0.1f;
    u = fminf(fmaxf(u, -0.1f), 0.1f);
    out[i] = 0.9f * mem[i] + u;
}

// ---------------- host-side launcher ----------------
struct GArgs {
    const f16 *Ah, *Bh;
    float* C; f16* Ch;
    int M, N, K, Arow, Brow, ldc;
    float alpha; int ep;
    const float* bias; long biasZ; const float* R;
    int nRemap, kRemap, thresh, inner, batch;
    long Ai, Ao, Bi, Bo, Ci, Co;
    int TA, TB, SOFT, EXA;
    const float2* stat; float2* part; int slotTot;
    cudaStream_t st;
};

static void hg(const GArgs& a)
{
    #define HGCALL(BN, TA_, TB_, SO_, EX_, SMEM) \
        hgemm<BN, 4, TA_, TB_, SO_, EX_><<<grid, 256, SMEM, a.st>>>( \
            a.Ah, a.Bh, a.C, a.Ch, a.K, a.Arow, a.Brow, a.ldc, \
            a.alpha, a.ep, a.bias, a.biasZ, a.R, a.nRemap, a.kRemap, a.thresh, \
            a.inner, a.Ai, a.Ao, a.Bi, a.Bo, a.Ci, a.Co, a.stat, a.part, a.slotTot)
    if (a.N % 128 == 0) {
        dim3 grid(a.N / 128, a.M / 128, a.batch);
        if (a.SOFT)        HGCALL(128, 0, 0, 1, 0, 81920);
        else if (a.EXA) {
            if (a.TA)      HGCALL(128, 1, 1, 0, 1, 81920);
            else           HGCALL(128, 0, 1, 0, 1, 81920);
        }
        else               HGCALL(128, 0, 0, 0, 0, 81920);
    } else {
        dim3 grid(a.N / 64, a.M / 128, a.batch);
        HGCALL(64, 0, 1, 0, 1, 61440);   // only the head-AV GEMM uses BN=64
    }
    #undef HGCALL
}

static void conv(const float* s, f16* h, long n, cudaStream_t st = 0)
{
    long n4h = n / 8;
    convert_kernel<<<(unsigned)((n4h + 255) / 256), 256, 0, st>>>(s, h, n4h);
}

extern "C" void kernel_launch(void* const* d_in, const int* in_sizes, int n_in,
                              void* d_out, int out_size)
{
    const float* tokens   = (const float*)d_in[0];
    const float* memories = (const float*)d_in[1];
    const float* ipw      = (const float*)d_in[2];
    const float* ipb      = (const float*)d_in[3];
    const float* opw      = (const float*)d_in[4];
    const float* opb      = (const float*)d_in[5];
    const float* w1       = (const float*)d_in[6];
    const float* b1       = (const float*)d_in[7];
    const float* w2       = (const float*)d_in[8];
    const float* b2       = (const float*)d_in[9];
    const float* n1w      = (const float*)d_in[10];
    const float* n1b      = (const float*)d_in[11];
    const float* n2w      = (const float*)d_in[12];
    const float* n2b      = (const float*)d_in[13];
    const float* aggw     = (const float*)d_in[14];
    const float* aggb     = (const float*)d_in[15];
    const float* gate     = (const float*)d_in[16];
    float* out = (float*)d_out;

    static bool inited = false;
    static cudaStream_t s2;
    static cudaEvent_t ev[4];
    if (!inited) {
        cudaFuncSetAttribute((const void*)hgemm<128, 4, 0, 0, 0, 0>, cudaFuncAttributeMaxDynamicSharedMemorySize, 81920);
        cudaFuncSetAttribute((const void*)hgemm<128, 4, 0, 0, 1, 0>, cudaFuncAttributeMaxDynamicSharedMemorySize, 81920);
        cudaFuncSetAttribute((const void*)hgemm<128, 4, 0, 1, 0, 1>, cudaFuncAttributeMaxDynamicSharedMemorySize, 81920);
        cudaFuncSetAttribute((const void*)hgemm<128, 4, 1, 1, 0, 1>, cudaFuncAttributeMaxDynamicSharedMemorySize, 81920);
        cudaFuncSetAttribute((const void*)hgemm<64, 4, 0, 1, 0, 1>,  cudaFuncAttributeMaxDynamicSharedMemorySize, 61440);
        cudaStreamCreateWithFlags(&s2, cudaStreamNonBlocking);
        for (int i = 0; i < 4; i++) cudaEventCreateWithFlags(&ev[i], cudaEventDisableTiming);
        inited = true;
    }

    float *xln, *x, *y, *upd4, *pooled, *gatew;
    float2 *part, *stat;
    cudaGetSymbolAddress((void**)&xln, g_xln);
    cudaGetSymbolAddress((void**)&x, g_x);
    cudaGetSymbolAddress((void**)&y, g_y);
    cudaGetSymbolAddress((void**)&upd4, g_upd4);
    cudaGetSymbolAddress((void**)&pooled, g_pooled);
    cudaGetSymbolAddress((void**)&gatew, g_gatew);
    cudaGetSymbolAddress((void**)&part, g_part);
    cudaGetSymbolAddress((void**)&stat, g_stat);

    f16 *xlnh, *xh, *qkvh, *sah, *ff1h, *sch, *retrph, *memh;
    f16 *ipwh, *opwh, *w1h, *w2h, *aggwh;
    cudaGetSymbolAddress((void**)&xlnh, g_xlnh);
    cudaGetSymbolAddress((void**)&xh, g_xh);
    cudaGetSymbolAddress((void**)&qkvh, g_qkvh);
    cudaGetSymbolAddress((void**)&sah, g_sah);
    cudaGetSymbolAddress((void**)&ff1h, g_ff1h);
    cudaGetSymbolAddress((void**)&sch, g_sch);
    cudaGetSymbolAddress((void**)&retrph, g_retrph);
    cudaGetSymbolAddress((void**)&memh, g_memh);
    cudaGetSymbolAddress((void**)&ipwh, g_ipwh);
    cudaGetSymbolAddress((void**)&opwh, g_opwh);
    cudaGetSymbolAddress((void**)&w1h, g_w1h);
    cudaGetSymbolAddress((void**)&w2h, g_w2h);
    cudaGetSymbolAddress((void**)&aggwh, g_aggwh);

    const float isd = 1.0f / sqrtf((float)DD);
    const long ND = (long)NTOK * DD;
    const long N3N = (long)NTOK * 3 * NTOK;
    const long NN = (long)NTOK * NTOK;
    const long NM = (long)NTOK * MMEM;

    // ---- fork side stream: weight/memory conversions ----
    cudaEventRecord(ev[0], 0);
    cudaStreamWaitEvent(s2, ev[0], 0);
    conv(ipw, ipwh, (long)EE * 3 * DD * DD, s2);
    conv(opw, opwh, (long)EE * DD * DD, s2);
    conv(w1, w1h, (long)EE * FFD * DD, s2);
    conv(w2, w2h, (long)EE * DD * FFD, s2);
    conv(aggw, aggwh, (long)DD * LL * DD, s2);
    conv(memories, memh, (long)LL * MMEM * DD, s2);
    cudaEventRecord(ev[1], s2);

    // ---- main: LN + cross attention ----
    ln_kernel<<<EE * NTOK, 128>>>(tokens, xln, nullptr, nullptr, xlnh, 0);

    // 1. cross scores -> f16 clipped + partials; reduce -> stats
    { GArgs a{}; a.Ah=xlnh; a.Bh=xlnh; a.Ch=sch;
      a.M=NTOK; a.N=3*NTOK; a.K=DD; a.Arow=DD; a.Brow=DD; a.ldc=3*NTOK;
      a.alpha=isd; a.ep=1; a.nRemap=1; a.thresh=-1; a.inner=1; a.batch=EE;
      a.Ao=ND; a.Co=N3N; a.SOFT=1; a.part=part; a.slotTot=(3*NTOK/128)*4; hg(a); }
    reduce_stats<<<EE * NTOK / 8, 256>>>(part, stat, (3 * NTOK / 128) * 4, EE * NTOK);
    // 2. x = xln_e + P @ ctx  (A = raw scores via EXA; B = xln native via TB, remap k)
    { GArgs a{}; a.Ah=sch; a.Bh=xlnh; a.C=x; a.Ch=xh;
      a.M=NTOK; a.N=DD; a.K=3*NTOK; a.Arow=3*NTOK; a.Brow=DD; a.ldc=DD;
      a.alpha=1.f; a.ep=6; a.R=xln; a.kRemap=1; a.thresh=-1; a.inner=1; a.batch=EE;
      a.Ao=N3N; a.Co=ND; a.TB=1; a.EXA=1; a.stat=stat; hg(a); }

    // join: qkv needs converted ipw
    cudaStreamWaitEvent(0, ev[1], 0);
    // 3. qkv
    { GArgs a{}; a.Ah=xh; a.Bh=ipwh; a.Ch=qkvh;
      a.M=NTOK; a.N=3*DD; a.K=DD; a.Arow=DD; a.Brow=DD; a.ldc=3*DD;
      a.alpha=1.f; a.ep=2; a.bias=ipb; a.biasZ=3*DD; a.inner=1; a.batch=EE;
      a.Ao=ND; a.Bo=(long)3*DD*DD; a.Co=(long)NTOK*3*DD; hg(a); }
    // 4. head scores -> f16 + partials; reduce
    { GArgs a{}; a.Ah=qkvh; a.Bh=qkvh + DD; a.Ch=sch;
      a.M=NTOK; a.N=NTOK; a.K=DHH; a.Arow=3*DD; a.Brow=3*DD; a.ldc=NTOK;
      a.alpha=0.125f; a.ep=0; a.inner=HH; a.batch=EE*HH;
      a.Ai=DHH; a.Ao=(long)NTOK*3*DD; a.Bi=DHH; a.Bo=(long)NTOK*3*DD;
      a.Ci=NN; a.Co=HH*NN; a.SOFT=1; a.part=part; a.slotTot=(NTOK/128)*4; hg(a); }
    reduce_stats<<<EE * HH * NTOK / 8, 256>>>(part, stat, (NTOK / 128) * 4, EE * HH * NTOK);
    // 5. sa = P @ V  (A = raw scores via EXA; B = V native via TB; batch e*H+h)
    { GArgs a{}; a.Ah=sch; a.Bh=qkvh + 2*DD; a.Ch=sah;
      a.M=NTOK; a.N=DHH; a.K=NTOK; a.Arow=NTOK; a.Brow=3*DD; a.ldc=DD;
      a.alpha=1.f; a.ep=0; a.inner=HH; a.batch=EE*HH;
      a.Ai=NN; a.Ao=HH*NN; a.Bi=DHH; a.Bo=(long)NTOK*3*DD;
      a.Ci=DHH; a.Co=ND; a.TB=1; a.EXA=1; a.stat=stat; hg(a); }
    // 6. out_proj + bias + residual
    { GArgs a{}; a.Ah=sah; a.Bh=opwh; a.C=y;
      a.M=NTOK; a.N=DD; a.K=DD; a.Arow=DD; a.Brow=DD; a.ldc=DD;
      a.alpha=1.f; a.ep=4; a.bias=opb; a.biasZ=DD; a.R=x; a.inner=1; a.batch=EE;
      a.Ao=ND; a.Bo=(long)DD*DD; a.Co=ND; hg(a); }
    ln_kernel<<<EE * NTOK, 128>>>(y, x, n1w, n1b, xh, 1);
    // 7. FFN
    { GArgs a{}; a.Ah=xh; a.Bh=w1h; a.Ch=ff1h;
      a.M=NTOK; a.N=FFD; a.K=DD; a.Arow=DD; a.Brow=DD; a.ldc=FFD;
      a.alpha=1.f; a.ep=3; a.bias=b1; a.biasZ=FFD; a.inner=1; a.batch=EE;
      a.Ao=ND; a.Bo=(long)FFD*DD; a.Co=(long)NTOK*FFD; hg(a); }
    { GArgs a{}; a.Ah=ff1h; a.Bh=w2h; a.C=y;
      a.M=NTOK; a.N=DD; a.K=FFD; a.Arow=FFD; a.Brow=FFD; a.ldc=DD;
      a.alpha=1.f; a.ep=4; a.bias=b2; a.biasZ=DD; a.R=x; a.inner=1; a.batch=EE;
      a.Ao=(long)NTOK*FFD; a.Bo=(long)DD*FFD; a.Co=ND; hg(a); }
    ln_kernel<<<EE * NTOK, 128>>>(y, x, n2w, n2b, xh, 1);

    // 8. memory scores -> f16 + partials; reduce (z = e*L + l)
    { GArgs a{}; a.Ah=xh; a.Bh=memh; a.Ch=sch;
      a.M=NTOK; a.N=MMEM; a.K=DD; a.Arow=DD; a.Brow=DD; a.ldc=MMEM;
      a.alpha=isd; a.ep=1; a.inner=LL; a.batch=EE*LL;
      a.Ai=0; a.Ao=ND; a.Bi=(long)MMEM*DD; a.Bo=0;
      a.Ci=NM; a.Co=LL*NM; a.SOFT=1; a.part=part; a.slotTot=(MMEM/128)*4; hg(a); }
    reduce_stats<<<EE * LL * NTOK / 8, 256>>>(part, stat, (MMEM / 128) * 4, EE * LL * NTOK);

    // fork: upd GEMM (A = raw scores via EXA+TA, B = xh via TB) + newmem on side stream
    cudaEventRecord(ev[2], 0);
    cudaStreamWaitEvent(s2, ev[2], 0);
    { GArgs a{}; a.Ah=sch; a.Bh=xh; a.C=upd4;
      a.M=MMEM; a.N=DD; a.K=NTOK; a.Arow=MMEM; a.Brow=DD; a.ldc=DD;
      a.alpha=1.f; a.ep=7; a.inner=LL; a.batch=EE*LL;
      a.Ai=NM; a.Ao=LL*NM; a.Bi=0; a.Bo=ND;
      a.Ci=(long)MMEM*DD; a.Co=(long)LL*MMEM*DD; a.TA=1; a.TB=1; a.EXA=1;
      a.stat=stat; a.st=s2; hg(a); }
    {
        long n = (long)LL * MMEM * DD;
        newmem_kernel<<<(unsigned)((n + 255) / 256), 256, 0, s2>>>(memories, upd4, out + ND + EE);
    }
    cudaEventRecord(ev[3], s2);

    // main: retr (A = raw scores via EXA; B = mem via TB) -> retrph permuted, agg, tail
    { GArgs a{}; a.Ah=sch; a.Bh=memh; a.Ch=retrph;
      a.M=NTOK; a.N=DD; a.K=MMEM; a.Arow=MMEM; a.Brow=DD; a.ldc=LL*DD;
      a.alpha=1.f; a.ep=0; a.inner=LL; a.batch=EE*LL;
      a.Ai=NM; a.Ao=LL*NM; a.Bi=(long)MMEM*DD; a.Bo=0;
      a.Ci=DD; a.Co=(long)NTOK*LL*DD; a.TB=1; a.EXA=1; a.stat=stat; hg(a); }
    { GArgs a{}; a.Ah=retrph; a.Bh=aggwh; a.C=x;
      a.M=NTOK; a.N=DD; a.K=LL*DD; a.Arow=LL*DD; a.Brow=LL*DD; a.ldc=DD;
      a.alpha=1.f; a.ep=4; a.bias=aggb; a.biasZ=0; a.R=x; a.inner=1; a.batch=EE;
      a.Ao=(long)NTOK*LL*DD; a.Co=ND; hg(a); }

    pool_kernel<<<(EE * DD + 255) / 256, 256>>>(x, pooled);
    gate_kernel<<<1, 128>>>(pooled, gate, out + ND, gatew);
    fused_kernel<<<(unsigned)((ND + 255) / 256), 256>>>(x, gatew, out);

    // join side stream
    cudaStreamWaitEvent(0, ev[3], 0);
}